// round 5
// baseline (speedup 1.0000x reference)
#include <cuda_runtime.h>

#define LAMBDA_COORD 5.0f
#define LAMBDA_NO_OBJ 0.5f

#define NTHREADS 1024
#define NBLOCKS  148    // one CTA per SM, single wave, all resident

__global__ void zero_out_kernel(float* out) {
    out[0] = 0.0f;
}

__device__ __forceinline__ float warp_reduce(float v) {
    #pragma unroll
    for (int off = 16; off > 0; off >>= 1)
        v += __shfl_xor_sync(0xFFFFFFFFu, v, off);
    return v;
}

__global__ void __launch_bounds__(NTHREADS)
yolo_loss_kernel(
    const float*  __restrict__ main_boxes,   // [M,4]
    const float4* __restrict__ pred_boxes,   // [P]
    const float*  __restrict__ conf,         // [P]
    const float4* __restrict__ gmp,          // [NP4]
    const float4* __restrict__ gpp,          // [NP4]
    const int*    __restrict__ matched_main, // [P]
    const float*  __restrict__ matched_iou,  // [P]
    float* __restrict__ out,
    int P, int NP4)
{
    const int tid = blockIdx.x * NTHREADS + threadIdx.x;   // 0 .. 151551
    const int S   = NBLOCKS * NTHREADS;                     // 151552

    float acc = 0.0f;

    // ================= front batch: issue ALL primary loads before compute ===
    // prob round 1: two strided float4-pairs, unconditionally in-bounds when
    // NP4 >= 2*S + tid's reach (true for this problem: NP4=327680 > 2*151552).
    bool two_deep = (tid + S) < NP4;

    float4 a0, b0, a1, b1;
    a0 = gmp[tid];
    b0 = gpp[tid];
    if (two_deep) {         // warp-uniform for this size (all true)
        a1 = gmp[tid + S];
        b1 = gpp[tid + S];
    }

    // box loads, overlapped in the same latency round (tid < P is warp-uniform)
    int   mm = 0;
    float c  = 0.0f, miou = 0.0f;
    float4 pb = make_float4(0.f, 0.f, 0.f, 0.f);
    bool has_box = tid < P;
    if (has_box) {
        mm   = matched_main[tid];
        c    = conf[tid];
        miou = matched_iou[tid];
        pb   = pred_boxes[tid];
    }

    // ================= compute on round-1 data =================
    {
        float d;
        d = a0.x - b0.x; acc = fmaf(d, d, acc);
        d = a0.y - b0.y; acc = fmaf(d, d, acc);
        d = a0.z - b0.z; acc = fmaf(d, d, acc);
        d = a0.w - b0.w; acc = fmaf(d, d, acc);
        if (two_deep) {
            d = a1.x - b1.x; acc = fmaf(d, d, acc);
            d = a1.y - b1.y; acc = fmaf(d, d, acc);
            d = a1.z - b1.z; acc = fmaf(d, d, acc);
            d = a1.w - b1.w; acc = fmaf(d, d, acc);
        }
    }

    if (has_box) {
        if (mm >= 0) {
            const float* mbp = main_boxes + (size_t)mm * 4;  // L2-resident gather
            float mx = mbp[0], my = mbp[1], mw = mbp[2], mh = mbp[3];

            float dx = mx - pb.x;
            float dy = my - pb.y;
            float xy = dx * dx + dy * dy;

            float sw = sqrtf(fmaxf(mw, 0.0f)) - sqrtf(fmaxf(pb.z, 0.0f));
            float sh = sqrtf(fmaxf(mh, 0.0f)) - sqrtf(fmaxf(pb.w, 0.0f));
            float wh = sw * sw + sh * sh;

            float di = miou - c;
            acc += LAMBDA_COORD * (xy + wh) + di * di;
        } else {
            acc += LAMBDA_NO_OBJ * c * c;
        }
    }

    // ================= remainder prob rounds (only tid < NP4 - 2S) ==========
    for (int i = tid + 2 * S; i < NP4; i += S) {
        float4 a = gmp[i];
        float4 b = gpp[i];
        float d;
        d = a.x - b.x; acc = fmaf(d, d, acc);
        d = a.y - b.y; acc = fmaf(d, d, acc);
        d = a.z - b.z; acc = fmaf(d, d, acc);
        d = a.w - b.w; acc = fmaf(d, d, acc);
    }

    // ================= block reduction + single atomic =================
    __shared__ float warp_sums[NTHREADS >> 5];
    float wsum = warp_reduce(acc);
    int lane = threadIdx.x & 31;
    int wid  = threadIdx.x >> 5;
    if (lane == 0) warp_sums[wid] = wsum;
    __syncthreads();

    if (wid == 0) {
        float v = (lane < (NTHREADS >> 5)) ? warp_sums[lane] : 0.0f;
        v = warp_reduce(v);
        if (lane == 0) atomicAdd(out, v);
    }
}

extern "C" void kernel_launch(void* const* d_in, const int* in_sizes, int n_in,
                              void* d_out, int out_size) {
    const float*  main_boxes   = (const float*) d_in[0];
    const float4* pred_boxes   = (const float4*)d_in[1];
    const float*  conf         = (const float*) d_in[2];
    const float4* gmp          = (const float4*)d_in[3];
    const float4* gpp          = (const float4*)d_in[4];
    const int*    matched_main = (const int*)   d_in[5];
    const float*  matched_iou  = (const float*) d_in[6];
    float* out = (float*)d_out;

    int P   = in_sizes[2];      // 32768
    int NP4 = in_sizes[3] / 4;  // 327680

    zero_out_kernel<<<1, 1>>>(out);
    yolo_loss_kernel<<<NBLOCKS, NTHREADS>>>(
        main_boxes, pred_boxes, conf, gmp, gpp, matched_main, matched_iou,
        out, P, NP4);
}

// round 6
// speedup vs baseline: 1.1272x; 1.1272x over previous
#include <cuda_runtime.h>

#define LAMBDA_COORD 5.0f
#define LAMBDA_NO_OBJ 0.5f

#define NTHREADS 1024
#define NBLOCKS  148    // one CTA per SM, single wave

__global__ void zero_out_kernel(float* out) {
    out[0] = 0.0f;
}

__device__ __forceinline__ float warp_reduce(float v) {
    #pragma unroll
    for (int off = 16; off > 0; off >>= 1)
        v += __shfl_xor_sync(0xFFFFFFFFu, v, off);
    return v;
}

__global__ void __launch_bounds__(NTHREADS)
yolo_loss_kernel(
    const float*  __restrict__ main_boxes,   // [M,4]
    const float4* __restrict__ pred_boxes,   // [P]
    const float*  __restrict__ conf,         // [P]
    const float4* __restrict__ gmp,          // [NP4]
    const float4* __restrict__ gpp,          // [NP4]
    const int*    __restrict__ matched_main, // [P]
    const float*  __restrict__ matched_iou,  // [P]
    float* __restrict__ out,
    int P, int NP4)
{
    const int tid = blockIdx.x * NTHREADS + threadIdx.x;   // 0 .. 151551
    const int S   = NBLOCKS * NTHREADS;                     // 151552

    float acc = 0.0f;

    // ===== ONE front batch: every load this thread will ever need, all
    // independent, issued before any compute. For this problem size:
    //   round0 (tid):       always valid (S < NP4)
    //   round1 (tid + S):   always valid (2S < NP4 + ... max tid+S = 303103 < 327680)
    //   round2 (tid + 2S):  only tid < NP4 - 2S = 24576  (blocks 0..23, uniform)
    bool deep1 = (tid +     S) < NP4;   // all true here, kept for generality
    bool deep2 = (tid + 2 * S) < NP4;   // first 24 blocks only (block-uniform)

    float4 a0, b0, a1, b1, a2, b2;
    a0 = gmp[tid];
    b0 = gpp[tid];
    if (deep1) { a1 = gmp[tid + S];     b1 = gpp[tid + S]; }
    if (deep2) { a2 = gmp[tid + 2 * S]; b2 = gpp[tid + 2 * S]; }

    // box loads in the same batch (tid < P covers blocks 0..31, block-uniform)
    int   mm = 0;
    float c  = 0.0f, miou = 0.0f;
    float4 pb = make_float4(0.f, 0.f, 0.f, 0.f);
    bool has_box = tid < P;
    if (has_box) {
        mm   = matched_main[tid];
        c    = conf[tid];
        miou = matched_iou[tid];
        pb   = pred_boxes[tid];
    }

    // ===== compute =====
    {
        float d;
        d = a0.x - b0.x; acc = fmaf(d, d, acc);
        d = a0.y - b0.y; acc = fmaf(d, d, acc);
        d = a0.z - b0.z; acc = fmaf(d, d, acc);
        d = a0.w - b0.w; acc = fmaf(d, d, acc);
        if (deep1) {
            d = a1.x - b1.x; acc = fmaf(d, d, acc);
            d = a1.y - b1.y; acc = fmaf(d, d, acc);
            d = a1.z - b1.z; acc = fmaf(d, d, acc);
            d = a1.w - b1.w; acc = fmaf(d, d, acc);
        }
        if (deep2) {
            d = a2.x - b2.x; acc = fmaf(d, d, acc);
            d = a2.y - b2.y; acc = fmaf(d, d, acc);
            d = a2.z - b2.z; acc = fmaf(d, d, acc);
            d = a2.w - b2.w; acc = fmaf(d, d, acc);
        }
    }

    if (has_box) {
        if (mm >= 0) {
            const float* mbp = main_boxes + (size_t)mm * 4;  // 16KB table, L2/L1 hits
            float mx = mbp[0], my = mbp[1], mw = mbp[2], mh = mbp[3];

            float dx = mx - pb.x;
            float dy = my - pb.y;
            float xy = dx * dx + dy * dy;

            float sw = sqrtf(fmaxf(mw, 0.0f)) - sqrtf(fmaxf(pb.z, 0.0f));
            float sh = sqrtf(fmaxf(mh, 0.0f)) - sqrtf(fmaxf(pb.w, 0.0f));
            float wh = sw * sw + sh * sh;

            float di = miou - c;
            acc += LAMBDA_COORD * (xy + wh) + di * di;
        } else {
            acc += LAMBDA_NO_OBJ * c * c;
        }
    }

    // ===== block reduction + one atomic per block =====
    __shared__ float warp_sums[NTHREADS >> 5];
    float wsum = warp_reduce(acc);
    int lane = threadIdx.x & 31;
    int wid  = threadIdx.x >> 5;
    if (lane == 0) warp_sums[wid] = wsum;
    __syncthreads();

    if (wid == 0) {
        float v = (lane < (NTHREADS >> 5)) ? warp_sums[lane] : 0.0f;
        v = warp_reduce(v);
        if (lane == 0) atomicAdd(out, v);
    }
}

extern "C" void kernel_launch(void* const* d_in, const int* in_sizes, int n_in,
                              void* d_out, int out_size) {
    const float*  main_boxes   = (const float*) d_in[0];
    const float4* pred_boxes   = (const float4*)d_in[1];
    const float*  conf         = (const float*) d_in[2];
    const float4* gmp          = (const float4*)d_in[3];
    const float4* gpp          = (const float4*)d_in[4];
    const int*    matched_main = (const int*)   d_in[5];
    const float*  matched_iou  = (const float*) d_in[6];
    float* out = (float*)d_out;

    int P   = in_sizes[2];      // 32768
    int NP4 = in_sizes[3] / 4;  // 327680

    zero_out_kernel<<<1, 1>>>(out);
    yolo_loss_kernel<<<NBLOCKS, NTHREADS>>>(
        main_boxes, pred_boxes, conf, gmp, gpp, matched_main, matched_iou,
        out, P, NP4);
}

// round 7
// speedup vs baseline: 1.1422x; 1.0133x over previous
#include <cuda_runtime.h>

#define LAMBDA_COORD 5.0f
#define LAMBDA_NO_OBJ 0.5f

#define NTHREADS 1024
#define NBLOCKS  148    // one CTA per SM, single wave, level byte-load per block

__global__ void zero_out_kernel(float* out) {
    out[0] = 0.0f;
}

__device__ __forceinline__ float warp_reduce(float v) {
    #pragma unroll
    for (int off = 16; off > 0; off >>= 1)
        v += __shfl_xor_sync(0xFFFFFFFFu, v, off);
    return v;
}

__global__ void __launch_bounds__(NTHREADS)
yolo_loss_kernel(
    const float*  __restrict__ main_boxes,   // [M,4]
    const float4* __restrict__ pred_boxes,   // [P]
    const float*  __restrict__ conf,         // [P]
    const float4* __restrict__ gmp,          // [NP4]
    const float4* __restrict__ gpp,          // [NP4]
    const int*    __restrict__ matched_main, // [P]
    const float*  __restrict__ matched_iou,  // [P]
    float* __restrict__ out,
    int P, int NP4, int chunk, int bchunk)
{
    const int b  = blockIdx.x;
    const int tx = threadIdx.x;

    // ----- this block's contiguous slices -----
    const int pbase = b * chunk;                       // prob float4-pairs
    const int pend  = min(pbase + chunk, NP4);
    const int bbase = b * bchunk;                      // box items

    float acc = 0.0f;

    // ===== ONE independent front batch: 2-3 guarded prob rounds + box =====
    const int i0 = pbase + tx;
    const int i1 = i0 + NTHREADS;
    const int i2 = i1 + NTHREADS;
    const bool v0 = i0 < pend;
    const bool v1 = i1 < pend;
    const bool v2 = i2 < pend;

    float4 a0, c0, a1, c1, a2, c2;
    if (v0) { a0 = gmp[i0]; c0 = gpp[i0]; }
    if (v1) { a1 = gmp[i1]; c1 = gpp[i1]; }
    if (v2) { a2 = gmp[i2]; c2 = gpp[i2]; }

    const int  p       = bbase + tx;
    const bool has_box = (tx < bchunk) && (p < P);
    int   mm = 0;
    float cf = 0.0f, miou = 0.0f;
    float4 pb = make_float4(0.f, 0.f, 0.f, 0.f);
    if (has_box) {
        mm   = matched_main[p];
        cf   = conf[p];
        miou = matched_iou[p];
        pb   = pred_boxes[p];
    }

    // ===== compute =====
    float d;
    if (v0) {
        d = a0.x - c0.x; acc = fmaf(d, d, acc);
        d = a0.y - c0.y; acc = fmaf(d, d, acc);
        d = a0.z - c0.z; acc = fmaf(d, d, acc);
        d = a0.w - c0.w; acc = fmaf(d, d, acc);
    }
    if (v1) {
        d = a1.x - c1.x; acc = fmaf(d, d, acc);
        d = a1.y - c1.y; acc = fmaf(d, d, acc);
        d = a1.z - c1.z; acc = fmaf(d, d, acc);
        d = a1.w - c1.w; acc = fmaf(d, d, acc);
    }
    if (v2) {
        d = a2.x - c2.x; acc = fmaf(d, d, acc);
        d = a2.y - c2.y; acc = fmaf(d, d, acc);
        d = a2.z - c2.z; acc = fmaf(d, d, acc);
        d = a2.w - c2.w; acc = fmaf(d, d, acc);
    }

    // generic spill loop (empty for this problem size: chunk <= 3*NTHREADS)
    for (int i = pbase + tx + 3 * NTHREADS; i < pend; i += NTHREADS) {
        float4 a = gmp[i];
        float4 c = gpp[i];
        d = a.x - c.x; acc = fmaf(d, d, acc);
        d = a.y - c.y; acc = fmaf(d, d, acc);
        d = a.z - c.z; acc = fmaf(d, d, acc);
        d = a.w - c.w; acc = fmaf(d, d, acc);
    }

    if (has_box) {
        if (mm >= 0) {
            const float* mbp = main_boxes + (size_t)mm * 4;  // 16KB table -> cache hits
            float mx = mbp[0], my = mbp[1], mw = mbp[2], mh = mbp[3];

            float dx = mx - pb.x;
            float dy = my - pb.y;
            float xy = dx * dx + dy * dy;

            float sw = sqrtf(fmaxf(mw, 0.0f)) - sqrtf(fmaxf(pb.z, 0.0f));
            float sh = sqrtf(fmaxf(mh, 0.0f)) - sqrtf(fmaxf(pb.w, 0.0f));
            float wh = sw * sw + sh * sh;

            float di = miou - cf;
            acc += LAMBDA_COORD * (xy + wh) + di * di;
        } else {
            acc += LAMBDA_NO_OBJ * cf * cf;
        }
    }

    // generic box spill loop (empty here: bchunk <= NTHREADS)
    for (int q = bbase + tx + NTHREADS; q < min(bbase + bchunk, P); q += NTHREADS) {
        int   m2 = matched_main[q];
        float c2f = conf[q];
        if (m2 >= 0) {
            float4 pq = pred_boxes[q];
            const float* mbp = main_boxes + (size_t)m2 * 4;
            float dx = mbp[0] - pq.x;
            float dy = mbp[1] - pq.y;
            float sw = sqrtf(fmaxf(mbp[2], 0.0f)) - sqrtf(fmaxf(pq.z, 0.0f));
            float sh = sqrtf(fmaxf(mbp[3], 0.0f)) - sqrtf(fmaxf(pq.w, 0.0f));
            float di = matched_iou[q] - c2f;
            acc += LAMBDA_COORD * (dx * dx + dy * dy + sw * sw + sh * sh) + di * di;
        } else {
            acc += LAMBDA_NO_OBJ * c2f * c2f;
        }
    }

    // ===== block reduction + one atomic per block =====
    __shared__ float warp_sums[NTHREADS >> 5];
    float wsum = warp_reduce(acc);
    int lane = tx & 31;
    int wid  = tx >> 5;
    if (lane == 0) warp_sums[wid] = wsum;
    __syncthreads();

    if (wid == 0) {
        float v = (lane < (NTHREADS >> 5)) ? warp_sums[lane] : 0.0f;
        v = warp_reduce(v);
        if (lane == 0) atomicAdd(out, v);
    }
}

extern "C" void kernel_launch(void* const* d_in, const int* in_sizes, int n_in,
                              void* d_out, int out_size) {
    const float*  main_boxes   = (const float*) d_in[0];
    const float4* pred_boxes   = (const float4*)d_in[1];
    const float*  conf         = (const float*) d_in[2];
    const float4* gmp          = (const float4*)d_in[3];
    const float4* gpp          = (const float4*)d_in[4];
    const int*    matched_main = (const int*)   d_in[5];
    const float*  matched_iou  = (const float*) d_in[6];
    float* out = (float*)d_out;

    int P   = in_sizes[2];      // 32768
    int NP4 = in_sizes[3] / 4;  // 327680

    int chunk  = (NP4 + NBLOCKS - 1) / NBLOCKS;  // 2215
    int bchunk = (P   + NBLOCKS - 1) / NBLOCKS;  // 222

    zero_out_kernel<<<1, 1>>>(out);
    yolo_loss_kernel<<<NBLOCKS, NTHREADS>>>(
        main_boxes, pred_boxes, conf, gmp, gpp, matched_main, matched_iou,
        out, P, NP4, chunk, bchunk);
}